// round 2
// baseline (speedup 1.0000x reference)
#include <cuda_runtime.h>
#include <math.h>

static constexpr int N_ROWS = 8192;
static constexpr int A_ART  = 32;
static constexpr int D_DIM  = 768;
static constexpr int O_DIM  = 256;
static constexpr float LN_EPS = 1e-5f;

static constexpr int MT = 64;   // rows per CTA in projection kernel
static constexpr int KC = 16;   // k-chunk
static constexpr int HPITCH = 260;

// Scratch for pooled vectors (allocation-free: __device__ global).
// Zero-initialized at module load; rows with count==0 are never written and
// never used (kernel B overrides them with no_news) -> deterministic.
__device__ float g_pooled[(size_t)N_ROWS * D_DIM];

// ---------------------------------------------------------------------------
// counts dtype detection: jnp.int64 may have been silently downgraded to
// int32 by jax. If int64, every odd 32-bit word is 0 (counts in [0,32]).
// If int32, the odd words are counts of odd rows; P(all 32 sampled == 0) ~ 0.
// Deterministic for fixed input.
// ---------------------------------------------------------------------------
__device__ __forceinline__ bool counts_is_i64(const int* __restrict__ cw) {
    bool i64 = true;
    #pragma unroll
    for (int i = 0; i < 32; ++i)
        if (cw[2 * i + 1] != 0) i64 = false;
    return i64;
}

__device__ __forceinline__ int load_count(const int* __restrict__ cw, bool i64, int n) {
    return i64 ? cw[2 * n] : cw[n];
}

// ---------------------------------------------------------------------------
// Kernel A: masked attention softmax pooling. One CTA per row n.
// Valid articles staged once in SMEM (single HBM read serves scores+pool).
// ---------------------------------------------------------------------------
__global__ void __launch_bounds__(256, 2) pool_kernel(
    const float* __restrict__ articles,
    const int*   __restrict__ counts_w,
    const float* __restrict__ attn_w,
    const float* __restrict__ attn_b)
{
    extern __shared__ float s_art[];          // [32][768] (only first cnt rows used)
    __shared__ float s_scores[A_ART];
    __shared__ float s_wt[A_ART];

    const bool i64 = counts_is_i64(counts_w);
    const int n = blockIdx.x;
    const int cnt = load_count(counts_w, i64, n);
    if (cnt <= 0) return;                     // kernel B writes no_news for these

    const int tid  = threadIdx.x;
    const int wid  = tid >> 5;
    const int lane = tid & 31;

    const float4* aw4 = reinterpret_cast<const float4*>(attn_w);

    // Load valid articles (skip padding -> ~50% HBM traffic saved) and
    // compute attention scores on the fly. Warp w handles a = w, w+8, ...
    for (int a = wid; a < cnt; a += 8) {
        const float4* src = reinterpret_cast<const float4*>(
            articles + ((size_t)n * A_ART + a) * D_DIM);
        float4* dst = reinterpret_cast<float4*>(s_art + a * D_DIM);
        float part = 0.f;
        #pragma unroll
        for (int j = 0; j < 6; ++j) {         // 192 float4 per article
            const int idx = lane + 32 * j;
            const float4 v = src[idx];
            dst[idx] = v;
            const float4 w = aw4[idx];
            part += v.x * w.x + v.y * w.y + v.z * w.z + v.w * w.w;
        }
        #pragma unroll
        for (int o = 16; o > 0; o >>= 1)
            part += __shfl_xor_sync(0xffffffffu, part, o);
        if (lane == 0) s_scores[a] = part;
    }
    __syncthreads();

    // Softmax over the (valid) article axis, warp 0.
    if (wid == 0) {
        const float b = attn_b[0];
        float s = (lane < cnt) ? (s_scores[lane] + b) : -3.0e38f;
        float m = s;
        #pragma unroll
        for (int o = 16; o > 0; o >>= 1)
            m = fmaxf(m, __shfl_xor_sync(0xffffffffu, m, o));
        float e = (lane < cnt) ? expf(s - m) : 0.f;
        float sum = e;
        #pragma unroll
        for (int o = 16; o > 0; o >>= 1)
            sum += __shfl_xor_sync(0xffffffffu, sum, o);
        if (lane < cnt) s_wt[lane] = e / sum;
    }
    __syncthreads();

    // pooled[d] = sum_a w[a] * art[a][d]; 192 float4 across threads 0..191.
    if (tid < D_DIM / 4) {
        float4 acc = make_float4(0.f, 0.f, 0.f, 0.f);
        for (int a = 0; a < cnt; ++a) {
            const float wa = s_wt[a];                         // smem broadcast
            const float4 v = reinterpret_cast<const float4*>(s_art + a * D_DIM)[tid];
            acc.x = fmaf(wa, v.x, acc.x);
            acc.y = fmaf(wa, v.y, acc.y);
            acc.z = fmaf(wa, v.z, acc.z);
            acc.w = fmaf(wa, v.w, acc.w);
        }
        reinterpret_cast<float4*>(g_pooled + (size_t)n * D_DIM)[tid] = acc;
    }
}

// ---------------------------------------------------------------------------
// Kernel B: [8192,768] @ [768,256] + bias + LayerNorm + exact GELU + no_news.
// 64-row tiles, proj_w staged via SMEM (L2-resident), packed f32x2 FMA inner
// loop (fma.rn.f32x2 -> FFMA2, 128 FMA/SM/cyc instead of 64).
// ---------------------------------------------------------------------------
__device__ __forceinline__ unsigned long long pack2(float lo, float hi) {
    unsigned long long r;
    asm("mov.b64 %0, {%1, %2};" : "=l"(r) : "f"(lo), "f"(hi));
    return r;
}
__device__ __forceinline__ void ffma2(unsigned long long& d,
                                      unsigned long long a,
                                      unsigned long long b) {
    asm("fma.rn.f32x2 %0, %1, %2, %0;" : "+l"(d) : "l"(a), "l"(b));
}
__device__ __forceinline__ float2 unpack2(unsigned long long v) {
    float lo, hi;
    asm("mov.b64 {%0, %1}, %2;" : "=f"(lo), "=f"(hi) : "l"(v));
    return make_float2(lo, hi);
}

__global__ void __launch_bounds__(256, 1) proj_kernel(
    const int*   __restrict__ counts_w,
    const float* __restrict__ proj_w,     // [768][256] row-major
    const float* __restrict__ proj_b,
    const float* __restrict__ ln_w,
    const float* __restrict__ ln_b,
    const float* __restrict__ no_news,
    float*       __restrict__ out)
{
    extern __shared__ float dynB[];
    float* w_s = dynB;                          // [KC][256]
    float* p_s = dynB + KC * O_DIM;             // [MT][KC]
    float* h_s = dynB + KC * O_DIM + MT * KC;   // [MT][HPITCH]

    const bool i64 = counts_is_i64(counts_w);
    const int tid  = threadIdx.x;
    const int row0 = blockIdx.x * MT;
    const int cg = tid & 31;                    // cols c0..c0+7
    const int rg = tid >> 5;                    // rows r0..r0+7
    const int c0 = cg * 8;
    const int r0 = rg * 8;

    unsigned long long acc[8][4];               // 8 rows x 8 cols (4 f32x2 pairs)
    #pragma unroll
    for (int i = 0; i < 8; ++i)
        #pragma unroll
        for (int j = 0; j < 4; ++j) acc[i][j] = 0ull;

    const float4* pw4 = reinterpret_cast<const float4*>(proj_w);

    for (int k0 = 0; k0 < D_DIM; k0 += KC) {
        // stage weight chunk: KC*256 floats = 1024 float4, 4 per thread
        #pragma unroll
        for (int j = 0; j < 4; ++j) {
            const int idx = tid + 256 * j;
            reinterpret_cast<float4*>(w_s)[idx] = pw4[(size_t)k0 * (O_DIM / 4) + idx];
        }
        // stage pooled chunk: MT*KC floats = 256 float4, 1 per thread
        {
            const int r  = tid >> 2;
            const int kq = tid & 3;
            reinterpret_cast<float4*>(p_s)[tid] =
                reinterpret_cast<const float4*>(g_pooled + (size_t)(row0 + r) * D_DIM + k0)[kq];
        }
        __syncthreads();

        #pragma unroll
        for (int kk = 0; kk < KC; ++kk) {
            // adjacent columns are already packed pairs in smem
            const ulonglong2 w01 = *reinterpret_cast<const ulonglong2*>(&w_s[kk * O_DIM + c0]);
            const ulonglong2 w23 = *reinterpret_cast<const ulonglong2*>(&w_s[kk * O_DIM + c0 + 4]);
            #pragma unroll
            for (int i = 0; i < 8; ++i) {
                const float p = p_s[(r0 + i) * KC + kk];   // warp-uniform broadcast
                const unsigned long long pp = pack2(p, p);
                ffma2(acc[i][0], pp, w01.x);
                ffma2(acc[i][1], pp, w01.y);
                ffma2(acc[i][2], pp, w23.x);
                ffma2(acc[i][3], pp, w23.y);
            }
        }
        __syncthreads();
    }

    // add bias, park h tile in smem for the row-wise LN reduction
    const float4 b0 = reinterpret_cast<const float4*>(proj_b)[cg * 2];
    const float4 b1 = reinterpret_cast<const float4*>(proj_b)[cg * 2 + 1];
    #pragma unroll
    for (int i = 0; i < 8; ++i) {
        const float2 v0 = unpack2(acc[i][0]);
        const float2 v1 = unpack2(acc[i][1]);
        const float2 v2 = unpack2(acc[i][2]);
        const float2 v3 = unpack2(acc[i][3]);
        float* hr = &h_s[(r0 + i) * HPITCH + c0];
        hr[0] = v0.x + b0.x; hr[1] = v0.y + b0.y;
        hr[2] = v1.x + b0.z; hr[3] = v1.y + b0.w;
        hr[4] = v2.x + b1.x; hr[5] = v2.y + b1.y;
        hr[6] = v3.x + b1.z; hr[7] = v3.y + b1.w;
    }
    __syncthreads();

    // LayerNorm (two-pass, matches reference) + exact-erf GELU + no_news
    const int wid = tid >> 5, lane = tid & 31;
    for (int r = wid; r < MT; r += 8) {
        const int n = row0 + r;
        const float* hr = &h_s[r * HPITCH + lane * 8];
        float v[8];
        #pragma unroll
        for (int j = 0; j < 8; ++j) v[j] = hr[j];

        float s = 0.f;
        #pragma unroll
        for (int j = 0; j < 8; ++j) s += v[j];
        #pragma unroll
        for (int o = 16; o > 0; o >>= 1) s += __shfl_xor_sync(0xffffffffu, s, o);
        const float mu = s * (1.f / O_DIM);

        float sq = 0.f;
        #pragma unroll
        for (int j = 0; j < 8; ++j) { const float d = v[j] - mu; sq += d * d; }
        #pragma unroll
        for (int o = 16; o > 0; o >>= 1) sq += __shfl_xor_sync(0xffffffffu, sq, o);
        const float inv = rsqrtf(sq * (1.f / O_DIM) + LN_EPS);

        const int cnt = load_count(counts_w, i64, n);
        float res[8];
        #pragma unroll
        for (int j = 0; j < 8; ++j) {
            const int c = lane * 8 + j;
            if (cnt > 0) {
                const float x = (v[j] - mu) * inv * ln_w[c] + ln_b[c];
                res[j] = 0.5f * x * (1.f + erff(x * 0.70710678118654752f));
            } else {
                res[j] = no_news[c];
            }
        }
        float4* o4 = reinterpret_cast<float4*>(out + (size_t)n * O_DIM + lane * 8);
        o4[0] = make_float4(res[0], res[1], res[2], res[3]);
        o4[1] = make_float4(res[4], res[5], res[6], res[7]);
    }
}

// ---------------------------------------------------------------------------
extern "C" void kernel_launch(void* const* d_in, const int* in_sizes, int n_in,
                              void* d_out, int out_size)
{
    const float* articles = (const float*)d_in[0];
    const int*   counts_w = (const int*)d_in[1];   // int32 or int64 words, detected on device
    const float* attn_w   = (const float*)d_in[2];
    const float* attn_b   = (const float*)d_in[3];
    const float* proj_w   = (const float*)d_in[4];
    const float* proj_b   = (const float*)d_in[5];
    const float* ln_w     = (const float*)d_in[6];
    const float* ln_b     = (const float*)d_in[7];
    const float* no_news  = (const float*)d_in[8];
    float* out = (float*)d_out;

    const int smemA = A_ART * D_DIM * (int)sizeof(float);                       // 98304 B
    const int smemB = (KC * O_DIM + MT * KC + MT * HPITCH) * (int)sizeof(float);// 87040 B
    cudaFuncSetAttribute(pool_kernel, cudaFuncAttributeMaxDynamicSharedMemorySize, smemA);
    cudaFuncSetAttribute(proj_kernel, cudaFuncAttributeMaxDynamicSharedMemorySize, smemB);

    pool_kernel<<<N_ROWS, 256, smemA>>>(articles, counts_w, attn_w, attn_b);
    proj_kernel<<<N_ROWS / MT, 256, smemB>>>(counts_w, proj_w, proj_b,
                                             ln_w, ln_b, no_news, out);
}

// round 5
// speedup vs baseline: 1.0105x; 1.0105x over previous
#include <cuda_runtime.h>
#include <math.h>

static constexpr int N_ROWS = 8192;
static constexpr int A_ART  = 32;
static constexpr int D_DIM  = 768;
static constexpr int O_DIM  = 256;
static constexpr float LN_EPS = 1e-5f;

static constexpr int MT = 64;   // rows per CTA in projection kernel
static constexpr int KC = 16;   // k-chunk

// Scratch for pooled vectors (allocation-free: __device__ global).
__device__ float g_pooled[(size_t)N_ROWS * D_DIM];

// ---------------------------------------------------------------------------
// counts dtype detection (int64 silently downgraded to int32 by jax or not):
// if int64, all odd 32-bit words of the first 32 entries are zero.
// ---------------------------------------------------------------------------
__device__ __forceinline__ bool counts_is_i64(const int* __restrict__ cw) {
    bool i64 = true;
    #pragma unroll
    for (int i = 0; i < 32; ++i)
        if (cw[2 * i + 1] != 0) i64 = false;
    return i64;
}
__device__ __forceinline__ int load_count(const int* __restrict__ cw, bool i64, int n) {
    return i64 ? cw[2 * n] : cw[n];
}

__device__ __forceinline__ unsigned smem_u32(const void* p) {
    unsigned a;
    asm("{ .reg .u64 t; cvta.to.shared.u64 t, %1; cvt.u32.u64 %0, t; }"
        : "=r"(a) : "l"(p));
    return a;
}
__device__ __forceinline__ void cp16(unsigned dst, const void* src) {
    asm volatile("cp.async.cg.shared.global [%0], [%1], 16;"
                 :: "r"(dst), "l"(src));
}

// ---------------------------------------------------------------------------
// Kernel A: masked attention softmax pooling. One CTA per row n.
// All valid articles pulled in ONE cp.async burst (max MLP), then scores /
// softmax / weighted sum run out of SMEM while the co-resident CTA loads.
// ---------------------------------------------------------------------------
__global__ void __launch_bounds__(256, 2) pool_kernel(
    const float* __restrict__ articles,
    const int*   __restrict__ counts_w,
    const float* __restrict__ attn_w,
    const float* __restrict__ attn_b)
{
    extern __shared__ float s_art[];          // [32][768] (first cnt rows used)
    __shared__ float s_aw[D_DIM];
    __shared__ float s_scores[A_ART];
    __shared__ float s_wt[A_ART];

    const bool i64 = counts_is_i64(counts_w);
    const int n = blockIdx.x;
    const int cnt = load_count(counts_w, i64, n);
    if (cnt <= 0) return;                     // kernel B writes no_news

    const int tid  = threadIdx.x;
    const int wid  = tid >> 5;
    const int lane = tid & 31;

    // ---- one burst of 16B async copies for all valid articles ----
    const float* src = articles + (size_t)n * A_ART * D_DIM;
    const unsigned sbase = smem_u32(s_art);
    const int nf4 = cnt * (D_DIM / 4);        // <= 6144
    for (int idx = tid; idx < nf4; idx += 256)
        cp16(sbase + idx * 16, src + idx * 4);
    asm volatile("cp.async.commit_group;" ::: "memory");

    // prefetch attention weights into smem while copies fly
    if (tid < D_DIM / 4)
        reinterpret_cast<float4*>(s_aw)[tid] =
            reinterpret_cast<const float4*>(attn_w)[tid];

    asm volatile("cp.async.wait_group 0;" ::: "memory");
    __syncthreads();

    // ---- scores: warp per article ----
    for (int a = wid; a < cnt; a += 8) {
        const float4* v4 = reinterpret_cast<const float4*>(s_art + a * D_DIM);
        const float4* w4 = reinterpret_cast<const float4*>(s_aw);
        float part = 0.f;
        #pragma unroll
        for (int j = 0; j < 6; ++j) {
            const int idx = lane + 32 * j;
            const float4 v = v4[idx];
            const float4 w = w4[idx];
            part += v.x * w.x + v.y * w.y + v.z * w.z + v.w * w.w;
        }
        #pragma unroll
        for (int o = 16; o > 0; o >>= 1)
            part += __shfl_xor_sync(0xffffffffu, part, o);
        if (lane == 0) s_scores[a] = part;
    }
    __syncthreads();

    // ---- softmax over valid articles (warp 0) ----
    if (wid == 0) {
        const float b = attn_b[0];
        float s = (lane < cnt) ? (s_scores[lane] + b) : -3.0e38f;
        float m = s;
        #pragma unroll
        for (int o = 16; o > 0; o >>= 1)
            m = fmaxf(m, __shfl_xor_sync(0xffffffffu, m, o));
        float e = (lane < cnt) ? expf(s - m) : 0.f;
        float sum = e;
        #pragma unroll
        for (int o = 16; o > 0; o >>= 1)
            sum += __shfl_xor_sync(0xffffffffu, sum, o);
        if (lane < cnt) s_wt[lane] = e / sum;
    }
    __syncthreads();

    // ---- pooled[d] = sum_a w[a]*art[a][d] ----
    if (tid < D_DIM / 4) {
        float4 acc = make_float4(0.f, 0.f, 0.f, 0.f);
        for (int a = 0; a < cnt; ++a) {
            const float wa = s_wt[a];
            const float4 v = reinterpret_cast<const float4*>(s_art + a * D_DIM)[tid];
            acc.x = fmaf(wa, v.x, acc.x);
            acc.y = fmaf(wa, v.y, acc.y);
            acc.z = fmaf(wa, v.z, acc.z);
            acc.w = fmaf(wa, v.w, acc.w);
        }
        reinterpret_cast<float4*>(g_pooled + (size_t)n * D_DIM)[tid] = acc;
    }
}

// ---------------------------------------------------------------------------
// Kernel B: [8192,768] @ [768,256] + bias + LayerNorm + exact GELU + no_news.
// FFMA2 inner loop; pooled operand stored PRE-DUPLICATED as (p,p) u64 pairs
// so one broadcast LDS.128 feeds 2 k-steps with zero packing MOVs.
// LayerNorm fully in registers via warp shuffles (each row lives in 1 warp).
// ---------------------------------------------------------------------------
__device__ __forceinline__ unsigned long long pack2(float lo, float hi) {
    unsigned long long r;
    asm("mov.b64 %0, {%1, %2};" : "=l"(r) : "f"(lo), "f"(hi));
    return r;
}
__device__ __forceinline__ void ffma2(unsigned long long& d,
                                      unsigned long long a,
                                      unsigned long long b) {
    asm("fma.rn.f32x2 %0, %1, %2, %0;" : "+l"(d) : "l"(a), "l"(b));
}
__device__ __forceinline__ float2 unpack2(unsigned long long v) {
    float lo, hi;
    asm("mov.b64 {%0, %1}, %2;" : "=f"(lo), "=f"(hi) : "l"(v));
    return make_float2(lo, hi);
}

__global__ void __launch_bounds__(256) proj_kernel(
    const int*   __restrict__ counts_w,
    const float* __restrict__ proj_w,     // [768][256] row-major
    const float* __restrict__ proj_b,
    const float* __restrict__ ln_w,
    const float* __restrict__ ln_b,
    const float* __restrict__ no_news,
    float*       __restrict__ out)
{
    extern __shared__ float dynB[];
    float* w_s = dynB;                                         // [KC][256] floats
    unsigned long long* p2_s =
        reinterpret_cast<unsigned long long*>(dynB + KC * O_DIM); // [MT][KC] (p,p)

    const bool i64 = counts_is_i64(counts_w);
    const int tid  = threadIdx.x;
    const int row0 = blockIdx.x * MT;
    const int cg = tid & 31;                    // cols c0..c0+7 (lane)
    const int rg = tid >> 5;                    // rows r0..r0+7 (warp)
    const int c0 = cg * 8;
    const int r0 = rg * 8;

    unsigned long long acc[8][4];
    #pragma unroll
    for (int i = 0; i < 8; ++i)
        #pragma unroll
        for (int j = 0; j < 4; ++j) acc[i][j] = 0ull;

    const float4* pw4 = reinterpret_cast<const float4*>(proj_w);

    #pragma unroll 1
    for (int k0 = 0; k0 < D_DIM; k0 += KC) {
        // stage weight chunk: KC*256 floats = 1024 float4, 4 per thread
        #pragma unroll
        for (int j = 0; j < 4; ++j) {
            const int idx = tid + 256 * j;
            reinterpret_cast<float4*>(w_s)[idx] = pw4[(size_t)k0 * (O_DIM / 4) + idx];
        }
        // stage pooled chunk pre-duplicated: 64 rows x 16 k (1 float4 / thread)
        {
            const int r = tid >> 2;
            const int q = tid & 3;
            const float4 v = *reinterpret_cast<const float4*>(
                g_pooled + (size_t)(row0 + r) * D_DIM + k0 + q * 4);
            ulonglong2* dst = reinterpret_cast<ulonglong2*>(&p2_s[r * KC + q * 4]);
            dst[0] = make_ulonglong2(pack2(v.x, v.x), pack2(v.y, v.y));
            dst[1] = make_ulonglong2(pack2(v.z, v.z), pack2(v.w, v.w));
        }
        __syncthreads();

        #pragma unroll
        for (int kk2 = 0; kk2 < KC / 2; ++kk2) {
            ulonglong2 pv[8];
            #pragma unroll
            for (int i = 0; i < 8; ++i)       // broadcast LDS.128: (p,p) x 2 ks
                pv[i] = *reinterpret_cast<const ulonglong2*>(
                    &p2_s[(r0 + i) * KC + kk2 * 2]);
            #pragma unroll
            for (int s = 0; s < 2; ++s) {
                const float* wrow = &w_s[(kk2 * 2 + s) * O_DIM + c0];
                const ulonglong2 w01 = *reinterpret_cast<const ulonglong2*>(wrow);
                const ulonglong2 w23 = *reinterpret_cast<const ulonglong2*>(wrow + 4);
                #pragma unroll
                for (int i = 0; i < 8; ++i) {
                    const unsigned long long pp = s ? pv[i].y : pv[i].x;
                    ffma2(acc[i][0], pp, w01.x);
                    ffma2(acc[i][1], pp, w01.y);
                    ffma2(acc[i][2], pp, w23.x);
                    ffma2(acc[i][3], pp, w23.y);
                }
            }
        }
        __syncthreads();
    }

    // ---- epilogue: bias + LayerNorm (warp shuffles) + exact GELU ----
    const float4 b0  = reinterpret_cast<const float4*>(proj_b)[cg * 2];
    const float4 b1  = reinterpret_cast<const float4*>(proj_b)[cg * 2 + 1];
    const float4 lw0 = reinterpret_cast<const float4*>(ln_w)[cg * 2];
    const float4 lw1 = reinterpret_cast<const float4*>(ln_w)[cg * 2 + 1];
    const float4 lb0 = reinterpret_cast<const float4*>(ln_b)[cg * 2];
    const float4 lb1 = reinterpret_cast<const float4*>(ln_b)[cg * 2 + 1];

    #pragma unroll
    for (int i = 0; i < 8; ++i) {
        const float2 v0 = unpack2(acc[i][0]);
        const float2 v1 = unpack2(acc[i][1]);
        const float2 v2 = unpack2(acc[i][2]);
        const float2 v3 = unpack2(acc[i][3]);
        float h[8];
        h[0] = v0.x + b0.x; h[1] = v0.y + b0.y;
        h[2] = v1.x + b0.z; h[3] = v1.y + b0.w;
        h[4] = v2.x + b1.x; h[5] = v2.y + b1.y;
        h[6] = v3.x + b1.z; h[7] = v3.y + b1.w;

        float s = 0.f;
        #pragma unroll
        for (int j = 0; j < 8; ++j) s += h[j];
        #pragma unroll
        for (int o = 16; o > 0; o >>= 1) s += __shfl_xor_sync(0xffffffffu, s, o);
        const float mu = s * (1.f / O_DIM);

        float sq = 0.f;
        #pragma unroll
        for (int j = 0; j < 8; ++j) { const float d = h[j] - mu; sq += d * d; }
        #pragma unroll
        for (int o = 16; o > 0; o >>= 1) sq += __shfl_xor_sync(0xffffffffu, sq, o);
        const float inv = rsqrtf(sq * (1.f / O_DIM) + LN_EPS);

        const int n   = row0 + r0 + i;
        const int cnt = load_count(counts_w, i64, n);

        float res[8];
        if (cnt > 0) {
            const float lw[8] = {lw0.x, lw0.y, lw0.z, lw0.w, lw1.x, lw1.y, lw1.z, lw1.w};
            const float lb[8] = {lb0.x, lb0.y, lb0.z, lb0.w, lb1.x, lb1.y, lb1.z, lb1.w};
            #pragma unroll
            for (int j = 0; j < 8; ++j) {
                const float x = (h[j] - mu) * inv * lw[j] + lb[j];
                res[j] = 0.5f * x * (1.f + erff(x * 0.70710678118654752f));
            }
        } else {
            const float4 nn0 = reinterpret_cast<const float4*>(no_news)[cg * 2];
            const float4 nn1 = reinterpret_cast<const float4*>(no_news)[cg * 2 + 1];
            res[0] = nn0.x; res[1] = nn0.y; res[2] = nn0.z; res[3] = nn0.w;
            res[4] = nn1.x; res[5] = nn1.y; res[6] = nn1.z; res[7] = nn1.w;
        }
        float4* o4 = reinterpret_cast<float4*>(out + (size_t)n * O_DIM + c0);
        o4[0] = make_float4(res[0], res[1], res[2], res[3]);
        o4[1] = make_float4(res[4], res[5], res[6], res[7]);
    }
}

// ---------------------------------------------------------------------------
extern "C" void kernel_launch(void* const* d_in, const int* in_sizes, int n_in,
                              void* d_out, int out_size)
{
    const float* articles = (const float*)d_in[0];
    const int*   counts_w = (const int*)d_in[1];
    const float* attn_w   = (const float*)d_in[2];
    const float* attn_b   = (const float*)d_in[3];
    const float* proj_w   = (const float*)d_in[4];
    const float* proj_b   = (const float*)d_in[5];
    const float* ln_w     = (const float*)d_in[6];
    const float* ln_b     = (const float*)d_in[7];
    const float* no_news  = (const float*)d_in[8];
    float* out = (float*)d_out;

    const int smemA = A_ART * D_DIM * (int)sizeof(float);                   // 98304 B
    const int smemB = KC * O_DIM * (int)sizeof(float) + MT * KC * 8;        // 24576 B
    cudaFuncSetAttribute(pool_kernel, cudaFuncAttributeMaxDynamicSharedMemorySize, smemA);
    cudaFuncSetAttribute(proj_kernel, cudaFuncAttributeMaxDynamicSharedMemorySize, smemB);

    pool_kernel<<<N_ROWS, 256, smemA>>>(articles, counts_w, attn_w, attn_b);
    proj_kernel<<<N_ROWS / MT, 256, smemB>>>(counts_w, proj_w, proj_b,
                                             ln_w, ln_b, no_news, out);
}